// round 11
// baseline (speedup 1.0000x reference)
#include <cuda_runtime.h>
#include <cstdint>

#define NB 4
#define NS 2048
#define ND 128
#define NDL 16
#define NTOP 8

#define NSEG 64
#define QSEG (NS / NSEG)   // 32

#define KSPLIT 2
#define KHALF (NS / KSPLIT)   // 1024

typedef unsigned long long ull;

// ---- scratch (device globals; no allocation allowed) ----
__device__ float g_qlow[NB * NS * NDL];
__device__ float g_klow[NB * NS * NDL];
__device__ float g_sh[NB * NS];
__device__ float g_S[(size_t)NB * NS * NS];          // scores, then exp(scores)
__device__ float g_psum[NSEG * NB * NS];             // column partial sums
__device__ float g_cinv[NB * NS];
__device__ float g_po[KSPLIT][NB * NS * ND];         // split-k partial outputs

__device__ __forceinline__ float neg_inf() { return __int_as_float(0xff800000u); }

// ---- packed f32x2 helpers (FFMA2 path; ptxas won't emit this from C++) ----
__device__ __forceinline__ ull pack2(float lo, float hi) {
    ull r;
    asm("mov.b64 %0, {%1, %2};" : "=l"(r) : "f"(lo), "f"(hi));
    return r;
}
__device__ __forceinline__ ull pack2dup(float v) {
    ull r;
    asm("mov.b64 %0, {%1, %1};" : "=l"(r) : "f"(v));
    return r;
}
__device__ __forceinline__ void unpack2(ull v, float& lo, float& hi) {
    asm("mov.b64 {%0, %1}, %2;" : "=f"(lo), "=f"(hi) : "l"(v));
}
__device__ __forceinline__ void fma2(ull& acc, ull a, ull b) {
    asm("fma.rn.f32x2 %0, %1, %2, %0;" : "+l"(acc) : "l"(a), "l"(b));
}

// ============================================================
// K1: low/high projections + per-(b,k) correction scalar sh
// ============================================================
__global__ void __launch_bounds__(64) k_proj(
    const float* __restrict__ Q, const float* __restrict__ K,
    const float* __restrict__ Wql, const float* __restrict__ bql,
    const float* __restrict__ Wkl, const float* __restrict__ bkl,
    const float* __restrict__ Wqh, const float* __restrict__ bqh,
    const float* __restrict__ Wkh, const float* __restrict__ bkh)
{
    int row = blockIdx.x;          // b*NS + i
    int t = threadIdx.x;
    __shared__ float qr[ND];
    __shared__ float kr[ND];
    __shared__ float qh[NDL];
    __shared__ float kh[NDL];

    qr[t]      = Q[(size_t)row * ND + t];
    qr[t + 64] = Q[(size_t)row * ND + t + 64];
    kr[t]      = K[(size_t)row * ND + t];
    kr[t + 64] = K[(size_t)row * ND + t + 64];
    __syncthreads();

    int g = t >> 4, j = t & 15;
    if (g == 0) {
        float a = bql[j];
        #pragma unroll 8
        for (int e = 0; e < ND; e++) a += qr[e] * Wql[e * NDL + j];
        g_qlow[(size_t)row * NDL + j] = a;
    } else if (g == 1) {
        float a = bkl[j];
        #pragma unroll 8
        for (int e = 0; e < ND; e++) a += kr[e] * Wkl[e * NDL + j];
        g_klow[(size_t)row * NDL + j] = a;
    } else if (g == 2) {
        float a = bqh[j];
        #pragma unroll 8
        for (int e = 0; e < ND; e++) a += qr[e] * Wqh[e * NDL + j];
        qh[j] = a;
    } else {
        float a = bkh[j];
        #pragma unroll 8
        for (int e = 0; e < ND; e++) a += kr[e] * Wkh[e * NDL + j];
        kh[j] = a;
    }
    __syncthreads();

    if (t == 0) {
        float s = 0.f;
        #pragma unroll
        for (int j2 = 0; j2 < NDL; j2++) s += qh[j2] * kh[j2];
        g_sh[row] = 0.25f * s;    // scale = 1/sqrt(16)
    }
}

// ============================================================
// K2a: masked low-rank scores -> g_S  (f32x2 packed: 2 q rows per lane)
// ============================================================
__global__ void __launch_bounds__(256) k_scores(const int* __restrict__ VL)
{
    __shared__ __align__(16) float ks[128][20];
    __shared__ __align__(16) float Ss[32][132];
    __shared__ int vls[128];

    int b  = blockIdx.z;
    int q0 = blockIdx.y * 32;
    int k0 = blockIdx.x * 128;
    int t  = threadIdx.x;

    {
        const float4* src = (const float4*)(g_klow + ((size_t)b * NS + k0) * NDL);
        #pragma unroll
        for (int u = 0; u < 2; u++) {
            int p = t + u * 256;
            float4 v = src[p];
            *(float4*)&ks[p >> 2][(p & 3) * 4] = v;
        }
    }
    if (t < 128) {
        int vlc = VL[b * NS + k0 + t];
        vlc = vlc < 0 ? 0 : (vlc > NS - 1 ? NS - 1 : vlc);
        vls[t] = vlc;
    }
    __syncthreads();

    int tq = t >> 4;             // 0..15
    int kg = t & 15;             // 0..15
    int ql0 = tq * 2;
    int qg0 = q0 + ql0, qg1 = qg0 + 1;

    ull qp2[NDL];
    {
        const float4* qp = (const float4*)(g_qlow + ((size_t)b * NS + qg0) * NDL);
        #pragma unroll
        for (int u = 0; u < 4; u++) {
            float4 v = qp[u];       // row 0
            float4 w = qp[u + 4];   // row 1
            qp2[u * 4 + 0] = pack2(v.x, w.x);
            qp2[u * 4 + 1] = pack2(v.y, w.y);
            qp2[u * 4 + 2] = pack2(v.z, w.z);
            qp2[u * 4 + 3] = pack2(v.w, w.w);
        }
    }

    #pragma unroll
    for (int i = 0; i < 8; i++) {
        int kl = kg + 16 * i;
        ull acc = 0ull;
        #pragma unroll
        for (int u = 0; u < 4; u++) {
            float4 kv = *(const float4*)&ks[kl][u * 4];
            fma2(acc, qp2[u * 4 + 0], pack2dup(kv.x));
            fma2(acc, qp2[u * 4 + 1], pack2dup(kv.y));
            fma2(acc, qp2[u * 4 + 2], pack2dup(kv.z));
            fma2(acc, qp2[u * 4 + 3], pack2dup(kv.w));
        }
        float a0, a1;
        unpack2(acc, a0, a1);
        a0 *= 0.25f; a1 *= 0.25f;
        int vlc = vls[kl];
        if (vlc == qg0) a0 += -1e9f;
        if (vlc == qg1) a1 += -1e9f;
        Ss[ql0][kl]     = a0;
        Ss[ql0 + 1][kl] = a1;
    }
    __syncthreads();

    #pragma unroll
    for (int u = 0; u < 4; u++) {
        int p = t + u * 256;
        int row = p >> 5, cg = p & 31;
        float4 v = *(const float4*)&Ss[row][cg * 4];
        *(float4*)(g_S + ((size_t)b * NS + q0 + row) * NS + k0 + cg * 4) = v;
    }
}

// ============================================================
// K2b: per-row top-8 and scatter sh into g_S
// ============================================================
__global__ void __launch_bounds__(256) k_topk()
{
    int q = blockIdx.x, b = blockIdx.y;
    int t = threadIdx.x;
    __shared__ __align__(16) float wk[NS];
    __shared__ float rv[8];
    __shared__ int ri[8];
    __shared__ int s_mi;
    __shared__ int topIdx[NTOP];

    float* Srow = g_S + ((size_t)b * NS + q) * NS;
    #pragma unroll
    for (int u = 0; u < 2; u++) {
        int p = t + u * 256;
        ((float4*)wk)[p] = ((const float4*)Srow)[p];
    }
    __syncthreads();

    float lv = neg_inf(); int li = 0;
    #pragma unroll
    for (int i = 0; i < 8; i++) {
        int k = t + i * 256;
        float v = wk[k];
        if (v > lv) { lv = v; li = k; }
    }

    for (int r = 0; r < NTOP; r++) {
        float mv = lv; int mi = li;
        #pragma unroll
        for (int o = 16; o > 0; o >>= 1) {
            float ov = __shfl_xor_sync(0xffffffffu, mv, o);
            int   oi = __shfl_xor_sync(0xffffffffu, mi, o);
            if (ov > mv || (ov == mv && oi < mi)) { mv = ov; mi = oi; }
        }
        if ((t & 31) == 0) { rv[t >> 5] = mv; ri[t >> 5] = mi; }
        __syncthreads();
        if (t == 0) {
            #pragma unroll
            for (int w = 1; w < 8; w++)
                if (rv[w] > mv || (rv[w] == mv && ri[w] < mi)) { mv = rv[w]; mi = ri[w]; }
            topIdx[r] = mi;
            s_mi = mi;
        }
        __syncthreads();
        if (r < NTOP - 1) {
            int gm = s_mi;
            if ((gm & 255) == t) {      // only the owner rescans
                wk[gm] = neg_inf();
                lv = neg_inf(); li = 0;
                #pragma unroll
                for (int i = 0; i < 8; i++) {
                    int k = t + i * 256;
                    float v = wk[k];
                    if (v > lv) { lv = v; li = k; }
                }
            }
        }
    }

    if (t < NTOP) {
        int idx = topIdx[t];
        Srow[idx] = g_sh[b * NS + idx];
    }
}

// ============================================================
// K3a: exp in place + partial column sums over q-segments.
// Replay-safe: g_S fully rewritten by k_scores/k_topk each launch.
// grid (2, NB, NSEG); thread = one float4 of columns
// ============================================================
__global__ void __launch_bounds__(256) k_colpart()
{
    int k  = (blockIdx.x * 256 + threadIdx.x) * 4;
    int b  = blockIdx.y;
    int seg = blockIdx.z;
    float* Sb = g_S + (size_t)b * NS * NS;
    int q0 = seg * QSEG;

    float4 s = make_float4(0.f, 0.f, 0.f, 0.f);
    #pragma unroll 4
    for (int q = q0; q < q0 + QSEG; q++) {
        float4 v = *(const float4*)&Sb[(size_t)q * NS + k];
        float4 e;
        e.x = __expf(v.x); e.y = __expf(v.y);
        e.z = __expf(v.z); e.w = __expf(v.w);
        s.x += e.x; s.y += e.y; s.z += e.z; s.w += e.w;
        *(float4*)&Sb[(size_t)q * NS + k] = e;   // S := exp(S)
    }
    *(float4*)&g_psum[((size_t)seg * NB + b) * NS + k] = s;
}

// K3b: combine segments -> 1/colsum
__global__ void __launch_bounds__(256) k_colfin()
{
    int i = blockIdx.x * 256 + threadIdx.x;   // b*NS + k
    float s = 0.f;
    #pragma unroll 8
    for (int seg = 0; seg < NSEG; seg++)
        s += g_psum[(size_t)seg * (NB * NS) + i];
    g_cinv[i] = 1.0f / s;
}

// ============================================================
// K4: split-k partial out = sum_k E[q,k]*cinv[k]*V[b,k,:]
// HIGH-OCCUPANCY version: tile 32q x 128d, thread 4q x 4d,
// ~40 regs, 25 KB smem -> 4 blocks/SM (32 warps).
// grid (NS/32, NB, KSPLIT) = 512 blocks.
// ============================================================
__global__ void __launch_bounds__(256, 4) k_out(const float* __restrict__ V)
{
    __shared__ ull As2[32][36];                      // dup-packed E*cinv, 9 KB
    __shared__ __align__(16) float Vs[32][128];      // 16 KB

    int b  = blockIdx.y;
    int q0 = blockIdx.x * 32;
    int z  = blockIdx.z;
    int t  = threadIdx.x;
    int tx = t & 31;     // d group: d = tx*4
    int ty = t >> 5;     // q group: q = q0 + ty*4 + qq

    const float* Eb = g_S + (size_t)b * NS * NS;     // holds exp(S)
    const float* ci = g_cinv + b * NS;
    const float* Vb = V + (size_t)b * NS * ND;

    ull acc2[4][2];
    #pragma unroll
    for (int i = 0; i < 4; i++) { acc2[i][0] = 0ull; acc2[i][1] = 0ull; }

    int kbeg = z * KHALF, kend = kbeg + KHALF;
    for (int k0 = kbeg; k0 < kend; k0 += 32) {
        __syncthreads();
        // A tile 32x32: E*cinv dup-packed (256 float4, 1/thread)
        {
            int row = t >> 3, kg = (t & 7) * 4;
            float4 e4 = *(const float4*)&Eb[(size_t)(q0 + row) * NS + k0 + kg];
            float4 c4 = *(const float4*)&ci[k0 + kg];
            ull a0 = pack2dup(e4.x * c4.x);
            ull a1 = pack2dup(e4.y * c4.y);
            ull a2 = pack2dup(e4.z * c4.z);
            ull a3 = pack2dup(e4.w * c4.w);
            ulonglong2 p0; p0.x = a0; p0.y = a1;
            ulonglong2 p1; p1.x = a2; p1.y = a3;
            *(ulonglong2*)&As2[row][kg]     = p0;
            *(ulonglong2*)&As2[row][kg + 2] = p1;
        }
        // V tile 32x128 (1024 float4, 4/thread)
        #pragma unroll
        for (int u = 0; u < 4; u++) {
            int p = t + u * 256;
            int row = p >> 5, colg = p & 31;
            *(float4*)&Vs[row][colg * 4] =
                *(const float4*)&Vb[(size_t)(k0 + row) * ND + colg * 4];
        }
        __syncthreads();

        #pragma unroll
        for (int kk = 0; kk < 32; kk++) {
            ulonglong2 vv = *(const ulonglong2*)&Vs[kk][tx * 4];
            #pragma unroll
            for (int qq = 0; qq < 4; qq++) {
                ull aa = As2[ty * 4 + qq][kk];   // LDS64 broadcast (warp-uniform row)
                fma2(acc2[qq][0], aa, vv.x);
                fma2(acc2[qq][1], aa, vv.y);
            }
        }
    }

    float* po = g_po[z];
    #pragma unroll
    for (int qq = 0; qq < 4; qq++) {
        float4 o;
        unpack2(acc2[qq][0], o.x, o.y);
        unpack2(acc2[qq][1], o.z, o.w);
        *(float4*)&po[(size_t)((b * NS) + q0 + ty * 4 + qq) * ND + tx * 4] = o;
    }
}

// K5: add the two split-k halves -> final out
__global__ void __launch_bounds__(256) k_add(float* __restrict__ Out)
{
    int p = blockIdx.x * 256 + threadIdx.x;   // float4 index
    float4 a = ((const float4*)g_po[0])[p];
    float4 c = ((const float4*)g_po[1])[p];
    a.x += c.x; a.y += c.y; a.z += c.z; a.w += c.w;
    ((float4*)Out)[p] = a;
}

// ============================================================
extern "C" void kernel_launch(void* const* d_in, const int* in_sizes, int n_in,
                              void* d_out, int out_size)
{
    const float* Q   = (const float*)d_in[0];
    const float* K   = (const float*)d_in[1];
    const float* V   = (const float*)d_in[2];
    const int*   VL  = (const int*)d_in[3];
    const float* Wql = (const float*)d_in[4];
    const float* bql = (const float*)d_in[5];
    const float* Wkl = (const float*)d_in[6];
    const float* bkl = (const float*)d_in[7];
    const float* Wqh = (const float*)d_in[8];
    const float* bqh = (const float*)d_in[9];
    const float* Wkh = (const float*)d_in[10];
    const float* bkh = (const float*)d_in[11];
    float* out = (float*)d_out;

    k_proj<<<NB * NS, 64>>>(Q, K, Wql, bql, Wkl, bkl, Wqh, bqh, Wkh, bkh);

    dim3 g2(NS / 128, NS / 32, NB);
    k_scores<<<g2, 256>>>(VL);

    dim3 g2b(NS, NB);
    k_topk<<<g2b, 256>>>();

    dim3 g3(2, NB, NSEG);
    k_colpart<<<g3, 256>>>();
    k_colfin<<<(NB * NS) / 256, 256>>>();

    dim3 g4(NS / 32, NB, KSPLIT);
    k_out<<<g4, 256>>>(V);

    k_add<<<(NB * NS * ND) / 4 / 256, 256>>>(out);
}